// round 8
// baseline (speedup 1.0000x reference)
#include <cuda_runtime.h>
#include <cuda_bf16.h>
#include <math.h>
#include <stdint.h>

// GptOssTopKRouter via legacy mma.sync (bf16x3 split emulating fp32 GEMM).
// BM=64 rows/CTA, 2 CTAs/SM for latency hiding.
// logits = hidden[T,H] @ weight[E,H]^T + bias ; top-4 ; softmax over the 4.
// Output f32: scores [T,4] at 0, indices-as-float at out_size/2.
// Near-tie rows (adjacent top-5 gap < GAP_THRESH) re-ranked with fp64 dots.

#define TOPK 4
#define NCAND 6
#define GAP_THRESH 1e-3f

#define BM 64
#define BN 128
#define KC 32                 // k elements per chunk
#define LGS 132               // padded logits stride (floats)

// smem layout (bytes)
#define SM_BIAS     0                         // 512 B
#define SM_TILES    1024
#define A_TILE      4096                      // 64 rows x 32 bf16 (64 B/row)
#define B_TILE      8192                      // 128 rows x 32 bf16
#define OFF_AHI     0
#define OFF_ALO     4096
#define OFF_BHI     8192
#define OFF_BLO     16384
#define STAGE_BYTES 24576                     // Ahi,Alo,Bhi,Blo
#define SM_LOGITS   1024                      // aliases stages (after GEMM)
#define SMEM_TOTAL  (1024 + 2*STAGE_BYTES)    // 50176 (logits 64*132*4=33792 fits)

// swizzled byte offset within a tile: 64B rows, 16B units c16 in 0..3
__device__ __forceinline__ uint32_t swz(int row, int c16) {
    return (uint32_t)(row * 64 + ((c16 ^ ((row >> 1) & 3)) << 4));
}

__device__ __forceinline__ uint32_t smem_u32(const void* p){
    uint32_t a;
    asm("{ .reg .u64 t; cvta.to.shared.u64 t, %1; cvt.u32.u64 %0, t; }":"=r"(a):"l"(p));
    return a;
}

__device__ __forceinline__ void ldsm4(uint32_t r[4], uint32_t addr){
    asm volatile("ldmatrix.sync.aligned.m8n8.x4.shared.b16 {%0,%1,%2,%3}, [%4];"
        : "=r"(r[0]),"=r"(r[1]),"=r"(r[2]),"=r"(r[3]) : "r"(addr));
}

__device__ __forceinline__ void mma_bf16(float d[4], const uint32_t a[4], const uint32_t b[2]){
    asm volatile("mma.sync.aligned.m16n8k16.row.col.f32.bf16.bf16.f32 "
        "{%0,%1,%2,%3}, {%4,%5,%6,%7}, {%8,%9}, {%0,%1,%2,%3};"
        : "+f"(d[0]),"+f"(d[1]),"+f"(d[2]),"+f"(d[3])
        : "r"(a[0]),"r"(a[1]),"r"(a[2]),"r"(a[3]), "r"(b[0]),"r"(b[1]));
}

// split 8 fp32 into packed bf16x2 hi[4] / lo[4] (low half = even element)
__device__ __forceinline__ void split8(float4 f0, float4 f1, uint32_t hi[4], uint32_t lo[4]){
    float f[8] = {f0.x,f0.y,f0.z,f0.w,f1.x,f1.y,f1.z,f1.w};
#pragma unroll
    for (int i = 0; i < 4; i++) {
        uint32_t hp;
        asm("cvt.rn.bf16x2.f32 %0, %1, %2;" : "=r"(hp) : "f"(f[2*i+1]), "f"(f[2*i]));
        float h0 = __uint_as_float(hp << 16);
        float h1 = __uint_as_float(hp & 0xFFFF0000u);
        float l0 = f[2*i]   - h0;
        float l1 = f[2*i+1] - h1;
        uint32_t lp;
        asm("cvt.rn.bf16x2.f32 %0, %1, %2;" : "=r"(lp) : "f"(l1), "f"(l0));
        hi[i] = hp; lo[i] = lp;
    }
}

__global__ __launch_bounds__(256, 2)
void router_mma_kernel(const float* __restrict__ hidden,
                       const float* __restrict__ weight,
                       const float* __restrict__ bias,
                       float* __restrict__ out,
                       int T, int H, int E, int idx_base)
{
    extern __shared__ char smem[];
    float* bias_s = (float*)(smem + SM_BIAS);
    float* logits = (float*)(smem + SM_LOGITS);
    const uint32_t sbase = smem_u32(smem);

    const int tid  = threadIdx.x;
    const int wid  = tid >> 5;
    const int lane = tid & 31;
    const int row0 = blockIdx.x * BM;

    if (tid < BN) bias_s[tid] = bias[tid];

    // loader mapping: seg = 8-float (32B) unit. A: 64 rows x 4 segs = 256 -> 1/thread.
    // B: 128 rows x 4 segs = 512 -> 2/thread (rows r and r+64).
    const int lrow = tid >> 2;       // 0..63
    const int lq   = tid & 3;        // which 8-float segment

    // warp tile: 2 (M) x 4 (N) warps, each 32x32
    const int wm = (wid & 1) * 32;
    const int wn = (wid >> 1) * 32;

    float d[2][4][4];
#pragma unroll
    for (int mt = 0; mt < 2; mt++)
#pragma unroll
        for (int nt = 0; nt < 4; nt++)
#pragma unroll
            for (int k = 0; k < 4; k++) d[mt][nt][k] = 0.0f;

    float4 stg[6];

    // prologue: LDG chunk 0
    {
        const float* ap  = &hidden[(size_t)(row0 + lrow) * H + lq * 8];
        const float* bp0 = &weight[(size_t)lrow * H + lq * 8];
        const float* bp1 = &weight[(size_t)(lrow + 64) * H + lq * 8];
        stg[0] = *reinterpret_cast<const float4*>(ap);
        stg[1] = *reinterpret_cast<const float4*>(ap + 4);
        stg[2] = *reinterpret_cast<const float4*>(bp0);
        stg[3] = *reinterpret_cast<const float4*>(bp0 + 4);
        stg[4] = *reinterpret_cast<const float4*>(bp1);
        stg[5] = *reinterpret_cast<const float4*>(bp1 + 4);
    }

    const int nch = H / KC;    // 90
    for (int t = 0; t < nch; t++) {
        char* stage_p = smem + SM_TILES + (t & 1) * STAGE_BYTES;
        const uint32_t stage_a = sbase + SM_TILES + (t & 1) * STAGE_BYTES;

        // ---- convert + STS (A hi/lo, B hi/lo) ----
        {
            uint32_t hi[4], lo[4];
            uint32_t offA = swz(lrow, lq);
            split8(stg[0], stg[1], hi, lo);
            *reinterpret_cast<uint4*>(stage_p + OFF_AHI + offA) = make_uint4(hi[0],hi[1],hi[2],hi[3]);
            *reinterpret_cast<uint4*>(stage_p + OFF_ALO + offA) = make_uint4(lo[0],lo[1],lo[2],lo[3]);
            uint32_t offB0 = swz(lrow, lq);
            split8(stg[2], stg[3], hi, lo);
            *reinterpret_cast<uint4*>(stage_p + OFF_BHI + offB0) = make_uint4(hi[0],hi[1],hi[2],hi[3]);
            *reinterpret_cast<uint4*>(stage_p + OFF_BLO + offB0) = make_uint4(lo[0],lo[1],lo[2],lo[3]);
            uint32_t offB1 = swz(lrow + 64, lq);
            split8(stg[4], stg[5], hi, lo);
            *reinterpret_cast<uint4*>(stage_p + OFF_BHI + offB1) = make_uint4(hi[0],hi[1],hi[2],hi[3]);
            *reinterpret_cast<uint4*>(stage_p + OFF_BLO + offB1) = make_uint4(lo[0],lo[1],lo[2],lo[3]);
        }

        // ---- prefetch next chunk ----
        if (t + 1 < nch) {
            int kb = (t + 1) * KC;
            const float* ap  = &hidden[(size_t)(row0 + lrow) * H + kb + lq * 8];
            const float* bp0 = &weight[(size_t)lrow * H + kb + lq * 8];
            const float* bp1 = &weight[(size_t)(lrow + 64) * H + kb + lq * 8];
            stg[0] = *reinterpret_cast<const float4*>(ap);
            stg[1] = *reinterpret_cast<const float4*>(ap + 4);
            stg[2] = *reinterpret_cast<const float4*>(bp0);
            stg[3] = *reinterpret_cast<const float4*>(bp0 + 4);
            stg[4] = *reinterpret_cast<const float4*>(bp1);
            stg[5] = *reinterpret_cast<const float4*>(bp1 + 4);
        }

        __syncthreads();

        // ---- MMA phase: 2 k16 steps ----
#pragma unroll
        for (int s2 = 0; s2 < 2; s2++) {
            uint32_t Ah[2][4], Al[2][4], Bh[2][4], Bl[2][4];
#pragma unroll
            for (int mt = 0; mt < 2; mt++) {
                int r = wm + mt * 16 + (lane & 15);
                int c16 = 2 * s2 + (lane >> 4);
                uint32_t ao = swz(r, c16);
                ldsm4(Ah[mt], stage_a + OFF_AHI + ao);
                ldsm4(Al[mt], stage_a + OFF_ALO + ao);
            }
#pragma unroll
            for (int p = 0; p < 2; p++) {
                int nr = wn + p * 16 + (lane & 7) + ((lane >> 4) & 1) * 8;
                int c16 = 2 * s2 + ((lane >> 3) & 1);
                uint32_t bo = swz(nr, c16);
                ldsm4(Bh[p], stage_a + OFF_BHI + bo);
                ldsm4(Bl[p], stage_a + OFF_BLO + bo);
            }
            // hi*hi
#pragma unroll
            for (int mt = 0; mt < 2; mt++)
#pragma unroll
                for (int nt = 0; nt < 4; nt++)
                    mma_bf16(d[mt][nt], Ah[mt], &Bh[nt >> 1][(nt & 1) * 2]);
            // hi*lo
#pragma unroll
            for (int mt = 0; mt < 2; mt++)
#pragma unroll
                for (int nt = 0; nt < 4; nt++)
                    mma_bf16(d[mt][nt], Ah[mt], &Bl[nt >> 1][(nt & 1) * 2]);
            // lo*hi
#pragma unroll
            for (int mt = 0; mt < 2; mt++)
#pragma unroll
                for (int nt = 0; nt < 4; nt++)
                    mma_bf16(d[mt][nt], Al[mt], &Bh[nt >> 1][(nt & 1) * 2]);
        }
    }

    __syncthreads();   // all ldmatrix done before logits alias the stage buffers

    // ---- accum (+bias) -> smem logits[64][LGS] ----
#pragma unroll
    for (int mt = 0; mt < 2; mt++)
#pragma unroll
        for (int nt = 0; nt < 4; nt++) {
            int m = wm + mt * 16 + (lane >> 2);
            int n = wn + nt * 8 + 2 * (lane & 3);
            logits[m * LGS + n]           = d[mt][nt][0] + bias_s[n];
            logits[m * LGS + n + 1]       = d[mt][nt][1] + bias_s[n + 1];
            logits[(m + 8) * LGS + n]     = d[mt][nt][2] + bias_s[n];
            logits[(m + 8) * LGS + n + 1] = d[mt][nt][3] + bias_s[n + 1];
        }
    __syncthreads();

    // ---- per-row top-6 + softmax; warp w handles rows 8w..8w+7 ----
#pragma unroll 1
    for (int rr = 0; rr < 8; rr++) {
        const int r = wid * 8 + rr;
        const int row = row0 + r;
        float v[4];
        bool taken[4] = {false, false, false, false};
#pragma unroll
        for (int j = 0; j < 4; j++) v[j] = logits[r * LGS + lane + 32 * j];

        float topv[NCAND];
        int   topi[NCAND];
#pragma unroll 1
        for (int k = 0; k < NCAND; k++) {
            float bv = -INFINITY;
            int   bi = 0x7FFFFFFF;
#pragma unroll
            for (int j = 0; j < 4; j++)
                if (!taken[j] && v[j] > bv) { bv = v[j]; bi = lane + 32 * j; }
#pragma unroll
            for (int off = 16; off > 0; off >>= 1) {
                float ov = __shfl_xor_sync(0xFFFFFFFFu, bv, off);
                int   oi = __shfl_xor_sync(0xFFFFFFFFu, bi, off);
                if (ov > bv || (ov == bv && oi < bi)) { bv = ov; bi = oi; }
            }
            topv[k] = bv;
            topi[k] = bi;
            if ((bi & 31) == lane) taken[bi >> 5] = true;
        }

        bool need = (topv[0]-topv[1] < GAP_THRESH) || (topv[1]-topv[2] < GAP_THRESH) ||
                    (topv[2]-topv[3] < GAP_THRESH) || (topv[3]-topv[4] < GAP_THRESH);

        if (!need) {
            if (lane == 0) {
                float mx = topv[0];
                float e0 = expf(topv[0]-mx), e1 = expf(topv[1]-mx);
                float e2 = expf(topv[2]-mx), e3 = expf(topv[3]-mx);
                float inv = 1.0f / (e0+e1+e2+e3);
                float* so = out + (size_t)row * TOPK;
                so[0]=e0*inv; so[1]=e1*inv; so[2]=e2*inv; so[3]=e3*inv;
                float* io = out + idx_base + (size_t)row * TOPK;
                io[0]=(float)topi[0]; io[1]=(float)topi[1];
                io[2]=(float)topi[2]; io[3]=(float)topi[3];
            }
        } else {
            // fp64 refinement of the 6 candidates (whole warp participates)
            const float* hrow = hidden + (size_t)row * H;
            double rv[NCAND];
#pragma unroll 1
            for (int c = 0; c < NCAND; c++) {
                const float* wrow = weight + (size_t)topi[c] * H;
                double s0 = 0.0, s1 = 0.0;
                for (int j = lane; j < H; j += 64) {
                    s0 = fma((double)hrow[j],      (double)wrow[j],      s0);
                    s1 = fma((double)hrow[j + 32], (double)wrow[j + 32], s1);
                }
                double acc = s0 + s1;
#pragma unroll
                for (int off = 16; off > 0; off >>= 1)
                    acc += __shfl_xor_sync(0xFFFFFFFFu, acc, off);
                rv[c] = acc + (double)bias[topi[c]];
            }
            if (lane == 0) {
                int ri[NCAND];
#pragma unroll
                for (int c = 0; c < NCAND; c++) ri[c] = topi[c];
#pragma unroll
                for (int a = 0; a < TOPK; a++) {
                    int best = a;
#pragma unroll
                    for (int b = a + 1; b < NCAND; b++)
                        if (rv[b] > rv[best] || (rv[b] == rv[best] && ri[b] < ri[best])) best = b;
                    double tvv = rv[a]; rv[a] = rv[best]; rv[best] = tvv;
                    int    tii = ri[a]; ri[a] = ri[best]; ri[best] = tii;
                }
                double mx = rv[0];
                float e0 = expf((float)(rv[0]-mx)), e1 = expf((float)(rv[1]-mx));
                float e2 = expf((float)(rv[2]-mx)), e3 = expf((float)(rv[3]-mx));
                float inv = 1.0f / (e0+e1+e2+e3);
                float* so = out + (size_t)row * TOPK;
                so[0]=e0*inv; so[1]=e1*inv; so[2]=e2*inv; so[3]=e3*inv;
                float* io = out + idx_base + (size_t)row * TOPK;
                io[0]=(float)ri[0]; io[1]=(float)ri[1]; io[2]=(float)ri[2]; io[3]=(float)ri[3];
            }
        }
    }
}

extern "C" void kernel_launch(void* const* d_in, const int* in_sizes, int n_in,
                              void* d_out, int out_size)
{
    const float* hidden = (const float*)d_in[0];
    const float* weight = (const float*)d_in[1];
    const float* bias   = (const float*)d_in[2];
    float* out = (float*)d_out;

    const int E = in_sizes[2];                 // 128
    const int H = in_sizes[1] / E;             // 2880
    const int T = in_sizes[0] / H;             // 16384
    const int idx_base = out_size / 2;

    cudaFuncSetAttribute(router_mma_kernel,
                         cudaFuncAttributeMaxDynamicSharedMemorySize, SMEM_TOTAL);
    dim3 grid(T / BM);     // 256
    dim3 block(256);
    router_mma_kernel<<<grid, block, SMEM_TOTAL>>>(hidden, weight, bias, out, T, H, E, idx_base);
}

// round 9
// speedup vs baseline: 1.0119x; 1.0119x over previous
#include <cuda_runtime.h>
#include <cuda_bf16.h>
#include <math.h>
#include <stdint.h>

// GptOssTopKRouter via legacy mma.sync (bf16x3 split emulating fp32 GEMM).
// Weight pre-converted once to pre-swizzled bf16 hi/lo tiles in gmem;
// main kernel streams them with cp.async. Hidden converted in-line (touched once).
// logits = hidden[T,H] @ weight[E,H]^T + bias ; top-4 ; softmax over the 4.
// Output f32: scores [T,4] at 0, indices-as-float at out_size/2.
// Near-tie rows (adjacent top-5 gap < GAP_THRESH) re-ranked with fp64 dots.

#define TOPK 4
#define NCAND 6
#define GAP_THRESH 1e-3f

#define BM 64
#define BN 128
#define KC 32                 // k elements per chunk
#define LGS 132               // padded logits stride (floats)
#define MAXCH 128             // max K chunks supported (H/KC = 90 here)

// smem layout (bytes)
#define SM_BIAS     0                         // 512 B
#define SM_TILES    1024
#define OFF_AHI     0
#define OFF_ALO     4096
#define OFF_BHI     8192
#define OFF_BLO     16384
#define STAGE_BYTES 24576                     // Ahi,Alo,Bhi,Blo
#define SM_LOGITS   1024                      // aliases stages (after GEMM)
#define SMEM_TOTAL  (1024 + 2*STAGE_BYTES)    // 50176 (logits 64*132*4=33792 fits)

// pre-converted weight tiles: [chunk][8192 bytes], pre-swizzled
__device__ __align__(16) char g_wt_hi[MAXCH * 8192];
__device__ __align__(16) char g_wt_lo[MAXCH * 8192];

// swizzled byte offset within a tile: 64B rows, 16B units c16 in 0..3
__device__ __forceinline__ uint32_t swz(int row, int c16) {
    return (uint32_t)(row * 64 + ((c16 ^ ((row >> 1) & 3)) << 4));
}

__device__ __forceinline__ uint32_t smem_u32(const void* p){
    uint32_t a;
    asm("{ .reg .u64 t; cvta.to.shared.u64 t, %1; cvt.u32.u64 %0, t; }":"=r"(a):"l"(p));
    return a;
}

__device__ __forceinline__ void ldsm4(uint32_t r[4], uint32_t addr){
    asm volatile("ldmatrix.sync.aligned.m8n8.x4.shared.b16 {%0,%1,%2,%3}, [%4];"
        : "=r"(r[0]),"=r"(r[1]),"=r"(r[2]),"=r"(r[3]) : "r"(addr));
}

__device__ __forceinline__ void mma_bf16(float d[4], const uint32_t a[4], const uint32_t b[2]){
    asm volatile("mma.sync.aligned.m16n8k16.row.col.f32.bf16.bf16.f32 "
        "{%0,%1,%2,%3}, {%4,%5,%6,%7}, {%8,%9}, {%0,%1,%2,%3};"
        : "+f"(d[0]),"+f"(d[1]),"+f"(d[2]),"+f"(d[3])
        : "r"(a[0]),"r"(a[1]),"r"(a[2]),"r"(a[3]), "r"(b[0]),"r"(b[1]));
}

__device__ __forceinline__ void cpa16(uint32_t d, const void* s){
    asm volatile("cp.async.cg.shared.global [%0], [%1], 16;" :: "r"(d), "l"(s));
}

// split 8 fp32 into packed bf16x2 hi[4] / lo[4] (low half = even element)
__device__ __forceinline__ void split8(float4 f0, float4 f1, uint32_t hi[4], uint32_t lo[4]){
    float f[8] = {f0.x,f0.y,f0.z,f0.w,f1.x,f1.y,f1.z,f1.w};
#pragma unroll
    for (int i = 0; i < 4; i++) {
        uint32_t hp;
        asm("cvt.rn.bf16x2.f32 %0, %1, %2;" : "=r"(hp) : "f"(f[2*i+1]), "f"(f[2*i]));
        float h0 = __uint_as_float(hp << 16);
        float h1 = __uint_as_float(hp & 0xFFFF0000u);
        float l0 = f[2*i]   - h0;
        float l1 = f[2*i+1] - h1;
        uint32_t lp;
        asm("cvt.rn.bf16x2.f32 %0, %1, %2;" : "=r"(lp) : "f"(l1), "f"(l0));
        hi[i] = hp; lo[i] = lp;
    }
}

// ---- pre-pass: convert weight[128 x H] fp32 -> pre-swizzled bf16 hi/lo tiles ----
__global__ void convert_weight_kernel(const float* __restrict__ weight, int H)
{
    const int t  = blockIdx.x;         // chunk
    const int kb = t * KC;
#pragma unroll 1
    for (int u = threadIdx.x; u < 512; u += 256) {   // 128 rows x 4 segs
        int row = u >> 2, lq = u & 3;
        const float* bp = &weight[(size_t)row * H + kb + lq * 8];
        float4 f0 = *reinterpret_cast<const float4*>(bp);
        float4 f1 = *reinterpret_cast<const float4*>(bp + 4);
        uint32_t hi[4], lo[4];
        split8(f0, f1, hi, lo);
        uint32_t off = (uint32_t)t * 8192u + swz(row, lq);
        *reinterpret_cast<uint4*>(g_wt_hi + off) = make_uint4(hi[0],hi[1],hi[2],hi[3]);
        *reinterpret_cast<uint4*>(g_wt_lo + off) = make_uint4(lo[0],lo[1],lo[2],lo[3]);
    }
}

__global__ __launch_bounds__(256, 2)
void router_mma_kernel(const float* __restrict__ hidden,
                       const float* __restrict__ weight,
                       const float* __restrict__ bias,
                       float* __restrict__ out,
                       int T, int H, int E, int idx_base)
{
    extern __shared__ char smem[];
    float* bias_s = (float*)(smem + SM_BIAS);
    float* logits = (float*)(smem + SM_LOGITS);
    const uint32_t sbase = smem_u32(smem);

    const int tid  = threadIdx.x;
    const int wid  = tid >> 5;
    const int lane = tid & 31;
    const int row0 = blockIdx.x * BM;

    if (tid < BN) bias_s[tid] = bias[tid];

    // A loader mapping: 64 rows x 4 segs = 256 -> 1 seg/thread
    const int lrow = tid >> 2;       // 0..63
    const int lq   = tid & 3;        // 8-float segment

    // warp tile: 2 (M) x 4 (N) warps, each 32x32
    const int wm = (wid & 1) * 32;
    const int wn = (wid >> 1) * 32;

    float d[2][4][4];
#pragma unroll
    for (int mt = 0; mt < 2; mt++)
#pragma unroll
        for (int nt = 0; nt < 4; nt++)
#pragma unroll
            for (int k = 0; k < 4; k++) d[mt][nt][k] = 0.0f;

    float4 stg0, stg1;
    const int nch = H / KC;    // 90

    // ---- prologue: cp.async B chunk0 into stage0 ; LDG A chunk0 ----
    {
        uint32_t dH = sbase + SM_TILES + OFF_BHI + tid * 32;
        uint32_t dL = sbase + SM_TILES + OFF_BLO + tid * 32;
        const char* sH = g_wt_hi + tid * 32;
        const char* sL = g_wt_lo + tid * 32;
        cpa16(dH, sH); cpa16(dH + 16, sH + 16);
        cpa16(dL, sL); cpa16(dL + 16, sL + 16);
        asm volatile("cp.async.commit_group;" ::: "memory");

        const float* ap = &hidden[(size_t)(row0 + lrow) * H + lq * 8];
        stg0 = *reinterpret_cast<const float4*>(ap);
        stg1 = *reinterpret_cast<const float4*>(ap + 4);
    }

    for (int t = 0; t < nch; t++) {
        char* stage_p = smem + SM_TILES + (t & 1) * STAGE_BYTES;
        const uint32_t stage_a = sbase + SM_TILES + (t & 1) * STAGE_BYTES;

        // ---- 1. convert A(t) + STS ----
        {
            uint32_t hi[4], lo[4];
            uint32_t offA = swz(lrow, lq);
            split8(stg0, stg1, hi, lo);
            *reinterpret_cast<uint4*>(stage_p + OFF_AHI + offA) = make_uint4(hi[0],hi[1],hi[2],hi[3]);
            *reinterpret_cast<uint4*>(stage_p + OFF_ALO + offA) = make_uint4(lo[0],lo[1],lo[2],lo[3]);
        }

        // ---- 2. LDG A(t+1) ----
        if (t + 1 < nch) {
            int kb = (t + 1) * KC;
            const float* ap = &hidden[(size_t)(row0 + lrow) * H + kb + lq * 8];
            stg0 = *reinterpret_cast<const float4*>(ap);
            stg1 = *reinterpret_cast<const float4*>(ap + 4);
        }

        // ---- 3. B(t) arrived ; 4. publish ----
        asm volatile("cp.async.wait_group 0;" ::: "memory");
        __syncthreads();

        // ---- 5. cp.async B(t+1) into other stage (overlaps MMA) ----
        if (t + 1 < nch) {
            uint32_t st1 = sbase + SM_TILES + ((t + 1) & 1) * STAGE_BYTES;
            uint32_t dH = st1 + OFF_BHI + tid * 32;
            uint32_t dL = st1 + OFF_BLO + tid * 32;
            const char* sH = g_wt_hi + (size_t)(t + 1) * 8192 + tid * 32;
            const char* sL = g_wt_lo + (size_t)(t + 1) * 8192 + tid * 32;
            cpa16(dH, sH); cpa16(dH + 16, sH + 16);
            cpa16(dL, sL); cpa16(dL + 16, sL + 16);
            asm volatile("cp.async.commit_group;" ::: "memory");
        }

        // ---- 6. MMA phase: 2 k16 steps ----
#pragma unroll
        for (int s2 = 0; s2 < 2; s2++) {
            uint32_t Ah[2][4], Al[2][4], Bh[2][4], Bl[2][4];
#pragma unroll
            for (int mt = 0; mt < 2; mt++) {
                int r = wm + mt * 16 + (lane & 15);
                int c16 = 2 * s2 + (lane >> 4);
                uint32_t ao = swz(r, c16);
                ldsm4(Ah[mt], stage_a + OFF_AHI + ao);
                ldsm4(Al[mt], stage_a + OFF_ALO + ao);
            }
#pragma unroll
            for (int p = 0; p < 2; p++) {
                int nr = wn + p * 16 + (lane & 7) + ((lane >> 4) & 1) * 8;
                int c16 = 2 * s2 + ((lane >> 3) & 1);
                uint32_t bo = swz(nr, c16);
                ldsm4(Bh[p], stage_a + OFF_BHI + bo);
                ldsm4(Bl[p], stage_a + OFF_BLO + bo);
            }
            // hi*hi
#pragma unroll
            for (int mt = 0; mt < 2; mt++)
#pragma unroll
                for (int nt = 0; nt < 4; nt++)
                    mma_bf16(d[mt][nt], Ah[mt], &Bh[nt >> 1][(nt & 1) * 2]);
            // hi*lo
#pragma unroll
            for (int mt = 0; mt < 2; mt++)
#pragma unroll
                for (int nt = 0; nt < 4; nt++)
                    mma_bf16(d[mt][nt], Ah[mt], &Bl[nt >> 1][(nt & 1) * 2]);
            // lo*hi
#pragma unroll
            for (int mt = 0; mt < 2; mt++)
#pragma unroll
                for (int nt = 0; nt < 4; nt++)
                    mma_bf16(d[mt][nt], Al[mt], &Bh[nt >> 1][(nt & 1) * 2]);
        }
    }

    __syncthreads();   // all ldmatrix done before logits alias the stage buffers

    // ---- accum (+bias) -> smem logits[64][LGS] ----
#pragma unroll
    for (int mt = 0; mt < 2; mt++)
#pragma unroll
        for (int nt = 0; nt < 4; nt++) {
            int m = wm + mt * 16 + (lane >> 2);
            int n = wn + nt * 8 + 2 * (lane & 3);
            logits[m * LGS + n]           = d[mt][nt][0] + bias_s[n];
            logits[m * LGS + n + 1]       = d[mt][nt][1] + bias_s[n + 1];
            logits[(m + 8) * LGS + n]     = d[mt][nt][2] + bias_s[n];
            logits[(m + 8) * LGS + n + 1] = d[mt][nt][3] + bias_s[n + 1];
        }
    __syncthreads();

    // ---- per-row top-6 + softmax; warp w handles rows 8w..8w+7 ----
#pragma unroll 1
    for (int rr = 0; rr < 8; rr++) {
        const int r = wid * 8 + rr;
        const int row = row0 + r;
        float v[4];
        bool taken[4] = {false, false, false, false};
#pragma unroll
        for (int j = 0; j < 4; j++) v[j] = logits[r * LGS + lane + 32 * j];

        float topv[NCAND];
        int   topi[NCAND];
#pragma unroll 1
        for (int k = 0; k < NCAND; k++) {
            float bv = -INFINITY;
            int   bi = 0x7FFFFFFF;
#pragma unroll
            for (int j = 0; j < 4; j++)
                if (!taken[j] && v[j] > bv) { bv = v[j]; bi = lane + 32 * j; }
#pragma unroll
            for (int off = 16; off > 0; off >>= 1) {
                float ov = __shfl_xor_sync(0xFFFFFFFFu, bv, off);
                int   oi = __shfl_xor_sync(0xFFFFFFFFu, bi, off);
                if (ov > bv || (ov == bv && oi < bi)) { bv = ov; bi = oi; }
            }
            topv[k] = bv;
            topi[k] = bi;
            if ((bi & 31) == lane) taken[bi >> 5] = true;
        }

        bool need = (topv[0]-topv[1] < GAP_THRESH) || (topv[1]-topv[2] < GAP_THRESH) ||
                    (topv[2]-topv[3] < GAP_THRESH) || (topv[3]-topv[4] < GAP_THRESH);

        if (!need) {
            if (lane == 0) {
                float mx = topv[0];
                float e0 = expf(topv[0]-mx), e1 = expf(topv[1]-mx);
                float e2 = expf(topv[2]-mx), e3 = expf(topv[3]-mx);
                float inv = 1.0f / (e0+e1+e2+e3);
                float* so = out + (size_t)row * TOPK;
                so[0]=e0*inv; so[1]=e1*inv; so[2]=e2*inv; so[3]=e3*inv;
                float* io = out + idx_base + (size_t)row * TOPK;
                io[0]=(float)topi[0]; io[1]=(float)topi[1];
                io[2]=(float)topi[2]; io[3]=(float)topi[3];
            }
        } else {
            // fp64 refinement of the 6 candidates (whole warp participates)
            const float* hrow = hidden + (size_t)row * H;
            double rv[NCAND];
#pragma unroll 1
            for (int c = 0; c < NCAND; c++) {
                const float* wrow = weight + (size_t)topi[c] * H;
                double s0 = 0.0, s1 = 0.0;
                for (int j = lane; j < H; j += 64) {
                    s0 = fma((double)hrow[j],      (double)wrow[j],      s0);
                    s1 = fma((double)hrow[j + 32], (double)wrow[j + 32], s1);
                }
                double acc = s0 + s1;
#pragma unroll
                for (int off = 16; off > 0; off >>= 1)
                    acc += __shfl_xor_sync(0xFFFFFFFFu, acc, off);
                rv[c] = acc + (double)bias[topi[c]];
            }
            if (lane == 0) {
                int ri[NCAND];
#pragma unroll
                for (int c = 0; c < NCAND; c++) ri[c] = topi[c];
#pragma unroll
                for (int a = 0; a < TOPK; a++) {
                    int best = a;
#pragma unroll
                    for (int b = a + 1; b < NCAND; b++)
                        if (rv[b] > rv[best] || (rv[b] == rv[best] && ri[b] < ri[best])) best = b;
                    double tvv = rv[a]; rv[a] = rv[best]; rv[best] = tvv;
                    int    tii = ri[a]; ri[a] = ri[best]; ri[best] = tii;
                }
                double mx = rv[0];
                float e0 = expf((float)(rv[0]-mx)), e1 = expf((float)(rv[1]-mx));
                float e2 = expf((float)(rv[2]-mx)), e3 = expf((float)(rv[3]-mx));
                float inv = 1.0f / (e0+e1+e2+e3);
                float* so = out + (size_t)row * TOPK;
                so[0]=e0*inv; so[1]=e1*inv; so[2]=e2*inv; so[3]=e3*inv;
                float* io = out + idx_base + (size_t)row * TOPK;
                io[0]=(float)ri[0]; io[1]=(float)ri[1]; io[2]=(float)ri[2]; io[3]=(float)ri[3];
            }
        }
    }
}

extern "C" void kernel_launch(void* const* d_in, const int* in_sizes, int n_in,
                              void* d_out, int out_size)
{
    const float* hidden = (const float*)d_in[0];
    const float* weight = (const float*)d_in[1];
    const float* bias   = (const float*)d_in[2];
    float* out = (float*)d_out;

    const int E = in_sizes[2];                 // 128
    const int H = in_sizes[1] / E;             // 2880
    const int T = in_sizes[0] / H;             // 2880 -> 16384
    const int idx_base = out_size / 2;
    const int nch = H / KC;                    // 90

    convert_weight_kernel<<<nch, 256>>>(weight, H);

    cudaFuncSetAttribute(router_mma_kernel,
                         cudaFuncAttributeMaxDynamicSharedMemorySize, SMEM_TOTAL);
    dim3 grid(T / BM);     // 256
    dim3 block(256);
    router_mma_kernel<<<grid, block, SMEM_TOTAL>>>(hidden, weight, bias, out, T, H, E, idx_base);
}

// round 12
// speedup vs baseline: 1.0193x; 1.0073x over previous
#include <cuda_runtime.h>
#include <cuda_bf16.h>
#include <math.h>
#include <stdint.h>

// GptOssTopKRouter via legacy mma.sync (bf16x3 split emulating fp32 GEMM).
// KC=64 chunks (45 barriers), 512-thread CTA, BM=128, 4x4 warp grid.
// Weight pre-converted once to pre-swizzled bf16 hi/lo tiles; cp.async streamed.
// logits = hidden[T,H] @ weight[E,H]^T + bias ; top-4 ; softmax over the 4.
// Output f32: scores [T,4] at 0, indices-as-float at out_size/2.
// Near-tie rows (adjacent top-5 gap < GAP_THRESH) re-ranked with fp64 dots.

#define TOPK 4
#define NCAND 6
#define GAP_THRESH 1e-3f

#define BM 128
#define BN 128
#define KC 64                 // k elements per chunk
#define LGS 132               // padded logits stride (floats)
#define MAXCH 64              // max K chunks (H/KC = 45 here)

// smem layout (bytes)
#define SM_BIAS     0                         // 512 B
#define SM_TILES    1024
#define OFF_AHI     0
#define OFF_ALO     16384
#define OFF_BHI     32768
#define OFF_BLO     49152
#define STAGE_BYTES 65536                     // Ahi,Alo,Bhi,Blo (16KB each)
#define SM_LOGITS   1024                      // aliases stages (after GEMM)
#define SMEM_TOTAL  (1024 + 2*STAGE_BYTES)    // 132096 (logits 128*132*4=67584 fits)

// pre-converted weight tiles: [chunk][16384 bytes], pre-swizzled
__device__ __align__(16) char g_wt_hi[MAXCH * 16384];
__device__ __align__(16) char g_wt_lo[MAXCH * 16384];

// swizzled byte offset within a 128-rows x 128B tile: 16B unit c16 in 0..7
__device__ __forceinline__ uint32_t swz(int row, int c16) {
    return (uint32_t)(row * 128 + ((c16 ^ (row & 7)) << 4));
}

__device__ __forceinline__ uint32_t smem_u32(const void* p){
    uint32_t a;
    asm("{ .reg .u64 t; cvta.to.shared.u64 t, %1; cvt.u32.u64 %0, t; }":"=r"(a):"l"(p));
    return a;
}

__device__ __forceinline__ void ldsm4(uint32_t r[4], uint32_t addr){
    asm volatile("ldmatrix.sync.aligned.m8n8.x4.shared.b16 {%0,%1,%2,%3}, [%4];"
        : "=r"(r[0]),"=r"(r[1]),"=r"(r[2]),"=r"(r[3]) : "r"(addr));
}

__device__ __forceinline__ void mma_bf16(float d[4], const uint32_t a[4], const uint32_t b[2]){
    asm volatile("mma.sync.aligned.m16n8k16.row.col.f32.bf16.bf16.f32 "
        "{%0,%1,%2,%3}, {%4,%5,%6,%7}, {%8,%9}, {%0,%1,%2,%3};"
        : "+f"(d[0]),"+f"(d[1]),"+f"(d[2]),"+f"(d[3])
        : "r"(a[0]),"r"(a[1]),"r"(a[2]),"r"(a[3]), "r"(b[0]),"r"(b[1]));
}

__device__ __forceinline__ void cpa16(uint32_t d, const void* s){
    asm volatile("cp.async.cg.shared.global [%0], [%1], 16;" :: "r"(d), "l"(s));
}

// split 8 fp32 into packed bf16x2 hi[4] / lo[4] (low half = even element)
__device__ __forceinline__ void split8(float4 f0, float4 f1, uint32_t hi[4], uint32_t lo[4]){
    float f[8] = {f0.x,f0.y,f0.z,f0.w,f1.x,f1.y,f1.z,f1.w};
#pragma unroll
    for (int i = 0; i < 4; i++) {
        uint32_t hp;
        asm("cvt.rn.bf16x2.f32 %0, %1, %2;" : "=r"(hp) : "f"(f[2*i+1]), "f"(f[2*i]));
        float h0 = __uint_as_float(hp << 16);
        float h1 = __uint_as_float(hp & 0xFFFF0000u);
        float l0 = f[2*i]   - h0;
        float l1 = f[2*i+1] - h1;
        uint32_t lp;
        asm("cvt.rn.bf16x2.f32 %0, %1, %2;" : "=r"(lp) : "f"(l1), "f"(l0));
        hi[i] = hp; lo[i] = lp;
    }
}

// ---- pre-pass: convert weight[128 x H] fp32 -> pre-swizzled bf16 hi/lo tiles ----
__global__ void convert_weight_kernel(const float* __restrict__ weight, int H)
{
    const int t  = blockIdx.x;         // chunk
    const int kb = t * KC;
#pragma unroll 1
    for (int u = threadIdx.x; u < 1024; u += 256) {   // 128 rows x 8 segs
        int row = u >> 3, lq = u & 7;
        const float* bp = &weight[(size_t)row * H + kb + lq * 8];
        float4 f0 = *reinterpret_cast<const float4*>(bp);
        float4 f1 = *reinterpret_cast<const float4*>(bp + 4);
        uint32_t hi[4], lo[4];
        split8(f0, f1, hi, lo);
        uint32_t off = (uint32_t)t * 16384u + swz(row, lq);
        *reinterpret_cast<uint4*>(g_wt_hi + off) = make_uint4(hi[0],hi[1],hi[2],hi[3]);
        *reinterpret_cast<uint4*>(g_wt_lo + off) = make_uint4(lo[0],lo[1],lo[2],lo[3]);
    }
}

__global__ __launch_bounds__(512, 1)
void router_mma_kernel(const float* __restrict__ hidden,
                       const float* __restrict__ weight,
                       const float* __restrict__ bias,
                       float* __restrict__ out,
                       int T, int H, int E, int idx_base)
{
    extern __shared__ char smem[];
    float* bias_s = (float*)(smem + SM_BIAS);
    float* logits = (float*)(smem + SM_LOGITS);
    const uint32_t sbase = smem_u32(smem);

    const int tid  = threadIdx.x;
    const int wid  = tid >> 5;
    const int lane = tid & 31;
    const int row0 = blockIdx.x * BM;

    if (tid < BN) bias_s[tid] = bias[tid];

    // A loader: 128 rows x 8 segs = 1024 units; 2 per thread (tid, tid+512)
    const int r0l = tid >> 3,  q0 = tid & 7;           // unit tid
    const int r1l = (tid + 512) >> 3, q1 = tid & 7;    // unit tid+512 (same q)

    // warp grid 4x4, warp tile 32x32
    const int wm = (wid & 3) * 32;
    const int wn = (wid >> 2) * 32;

    float d[2][4][4];
#pragma unroll
    for (int mt = 0; mt < 2; mt++)
#pragma unroll
        for (int nt = 0; nt < 4; nt++)
#pragma unroll
            for (int k = 0; k < 4; k++) d[mt][nt][k] = 0.0f;

    float4 s00, s01, s10, s11;
    const int nch = H / KC;    // 45

    // ---- prologue: cp.async B chunk0 into stage0 ; LDG A chunk0 ----
    {
        uint32_t dH = sbase + SM_TILES + OFF_BHI + tid * 32;
        uint32_t dL = sbase + SM_TILES + OFF_BLO + tid * 32;
        const char* sH = g_wt_hi + tid * 32;
        const char* sL = g_wt_lo + tid * 32;
        cpa16(dH, sH); cpa16(dH + 16, sH + 16);
        cpa16(dL, sL); cpa16(dL + 16, sL + 16);
        asm volatile("cp.async.commit_group;" ::: "memory");

        const float* a0 = &hidden[(size_t)(row0 + r0l) * H + q0 * 8];
        const float* a1 = &hidden[(size_t)(row0 + r1l) * H + q1 * 8];
        s00 = *reinterpret_cast<const float4*>(a0);
        s01 = *reinterpret_cast<const float4*>(a0 + 4);
        s10 = *reinterpret_cast<const float4*>(a1);
        s11 = *reinterpret_cast<const float4*>(a1 + 4);
    }

    for (int t = 0; t < nch; t++) {
        char* stage_p = smem + SM_TILES + (t & 1) * STAGE_BYTES;
        const uint32_t stage_a = sbase + SM_TILES + (t & 1) * STAGE_BYTES;

        // ---- 1. convert A(t) + STS ----
        {
            uint32_t hi[4], lo[4];
            uint32_t o0 = swz(r0l, q0);
            split8(s00, s01, hi, lo);
            *reinterpret_cast<uint4*>(stage_p + OFF_AHI + o0) = make_uint4(hi[0],hi[1],hi[2],hi[3]);
            *reinterpret_cast<uint4*>(stage_p + OFF_ALO + o0) = make_uint4(lo[0],lo[1],lo[2],lo[3]);
            uint32_t o1 = swz(r1l, q1);
            split8(s10, s11, hi, lo);
            *reinterpret_cast<uint4*>(stage_p + OFF_AHI + o1) = make_uint4(hi[0],hi[1],hi[2],hi[3]);
            *reinterpret_cast<uint4*>(stage_p + OFF_ALO + o1) = make_uint4(lo[0],lo[1],lo[2],lo[3]);
        }

        // ---- 2. LDG A(t+1) ----
        if (t + 1 < nch) {
            int kb = (t + 1) * KC;
            const float* a0 = &hidden[(size_t)(row0 + r0l) * H + kb + q0 * 8];
            const float* a1 = &hidden[(size_t)(row0 + r1l) * H + kb + q1 * 8];
            s00 = *reinterpret_cast<const float4*>(a0);
            s01 = *reinterpret_cast<const float4*>(a0 + 4);
            s10 = *reinterpret_cast<const float4*>(a1);
            s11 = *reinterpret_cast<const float4*>(a1 + 4);
        }

        // ---- 3. B(t) arrived ; publish ----
        asm volatile("cp.async.wait_group 0;" ::: "memory");
        __syncthreads();

        // ---- 4. cp.async B(t+1) into other stage (overlaps MMA) ----
        if (t + 1 < nch) {
            uint32_t st1 = sbase + SM_TILES + ((t + 1) & 1) * STAGE_BYTES;
            uint32_t dH = st1 + OFF_BHI + tid * 32;
            uint32_t dL = st1 + OFF_BLO + tid * 32;
            const char* sH = g_wt_hi + (size_t)(t + 1) * 16384 + tid * 32;
            const char* sL = g_wt_lo + (size_t)(t + 1) * 16384 + tid * 32;
            cpa16(dH, sH); cpa16(dH + 16, sH + 16);
            cpa16(dL, sL); cpa16(dL + 16, sL + 16);
            asm volatile("cp.async.commit_group;" ::: "memory");
        }

        // ---- 5. MMA phase: 4 k16 steps ----
#pragma unroll
        for (int s2 = 0; s2 < 4; s2++) {
            uint32_t Ah[2][4], Al[2][4], Bh[2][4], Bl[2][4];
#pragma unroll
            for (int mt = 0; mt < 2; mt++) {
                int r = wm + mt * 16 + (lane & 15);
                int c16 = 2 * s2 + (lane >> 4);
                uint32_t ao = swz(r, c16);
                ldsm4(Ah[mt], stage_a + OFF_AHI + ao);
                ldsm4(Al[mt], stage_a + OFF_ALO + ao);
            }
#pragma unroll
            for (int p = 0; p < 2; p++) {
                int nr = wn + p * 16 + (lane & 7) + ((lane >> 4) & 1) * 8;
                int c16 = 2 * s2 + ((lane >> 3) & 1);
                uint32_t bo = swz(nr, c16);
                ldsm4(Bh[p], stage_a + OFF_BHI + bo);
                ldsm4(Bl[p], stage_a + OFF_BLO + bo);
            }
            // hi*hi
#pragma unroll
            for (int mt = 0; mt < 2; mt++)
#pragma unroll
                for (int nt = 0; nt < 4; nt++)
                    mma_bf16(d[mt][nt], Ah[mt], &Bh[nt >> 1][(nt & 1) * 2]);
            // hi*lo
#pragma unroll
            for (int mt = 0; mt < 2; mt++)
#pragma unroll
                for (int nt = 0; nt < 4; nt++)
                    mma_bf16(d[mt][nt], Ah[mt], &Bl[nt >> 1][(nt & 1) * 2]);
            // lo*hi
#pragma unroll
            for (int mt = 0; mt < 2; mt++)
#pragma unroll
                for (int nt = 0; nt < 4; nt++)
                    mma_bf16(d[mt][nt], Al[mt], &Bh[nt >> 1][(nt & 1) * 2]);
        }
    }

    __syncthreads();   // all ldmatrix done before logits alias the stage buffers

    // ---- accum (+bias) -> smem logits[128][LGS] ----
#pragma unroll
    for (int mt = 0; mt < 2; mt++)
#pragma unroll
        for (int nt = 0; nt < 4; nt++) {
            int m = wm + mt * 16 + (lane >> 2);
            int n = wn + nt * 8 + 2 * (lane & 3);
            logits[m * LGS + n]           = d[mt][nt][0] + bias_s[n];
            logits[m * LGS + n + 1]       = d[mt][nt][1] + bias_s[n + 1];
            logits[(m + 8) * LGS + n]     = d[mt][nt][2] + bias_s[n];
            logits[(m + 8) * LGS + n + 1] = d[mt][nt][3] + bias_s[n + 1];
        }
    __syncthreads();

    // ---- per-row top-6 + softmax; warp w handles rows 8w..8w+7 ----
#pragma unroll 1
    for (int rr = 0; rr < 8; rr++) {
        const int r = wid * 8 + rr;
        const int row = row0 + r;
        float v[4];
        bool taken[4] = {false, false, false, false};
#pragma unroll
        for (int j = 0; j < 4; j++) v[j] = logits[r * LGS + lane + 32 * j];

        float topv[NCAND];
        int   topi[NCAND];
#pragma unroll 1
        for (int k = 0; k < NCAND; k++) {
            float bv = -INFINITY;
            int   bi = 0x7FFFFFFF;
#pragma unroll
            for (int j = 0; j < 4; j++)
                if (!taken[j] && v[j] > bv) { bv = v[j]; bi = lane + 32 * j; }
#pragma unroll
            for (int off = 16; off > 0; off >>= 1) {
                float ov = __shfl_xor_sync(0xFFFFFFFFu, bv, off);
                int   oi = __shfl_xor_sync(0xFFFFFFFFu, bi, off);
                if (ov > bv || (ov == bv && oi < bi)) { bv = ov; bi = oi; }
            }
            topv[k] = bv;
            topi[k] = bi;
            if ((bi & 31) == lane) taken[bi >> 5] = true;
        }

        bool need = (topv[0]-topv[1] < GAP_THRESH) || (topv[1]-topv[2] < GAP_THRESH) ||
                    (topv[2]-topv[3] < GAP_THRESH) || (topv[3]-topv[4] < GAP_THRESH);

        if (!need) {
            if (lane == 0) {
                float mx = topv[0];
                float e0 = expf(topv[0]-mx), e1 = expf(topv[1]-mx);
                float e2 = expf(topv[2]-mx), e3 = expf(topv[3]-mx);
                float inv = 1.0f / (e0+e1+e2+e3);
                float* so = out + (size_t)row * TOPK;
                so[0]=e0*inv; so[1]=e1*inv; so[2]=e2*inv; so[3]=e3*inv;
                float* io = out + idx_base + (size_t)row * TOPK;
                io[0]=(float)topi[0]; io[1]=(float)topi[1];
                io[2]=(float)topi[2]; io[3]=(float)topi[3];
            }
        } else {
            // fp64 refinement of the 6 candidates (whole warp participates)
            const float* hrow = hidden + (size_t)row * H;
            double rv[NCAND];
#pragma unroll 1
            for (int c = 0; c < NCAND; c++) {
                const float* wrow = weight + (size_t)topi[c] * H;
                double s0 = 0.0, s1 = 0.0;
                for (int j = lane; j < H; j += 64) {
                    s0 = fma((double)hrow[j],      (double)wrow[j],      s0);
                    s1 = fma((double)hrow[j + 32], (double)wrow[j + 32], s1);
                }
                double acc = s0 + s1;
#pragma unroll
                for (int off = 16; off > 0; off >>= 1)
                    acc += __shfl_xor_sync(0xFFFFFFFFu, acc, off);
                rv[c] = acc + (double)bias[topi[c]];
            }
            if (lane == 0) {
                int ri[NCAND];
#pragma unroll
                for (int c = 0; c < NCAND; c++) ri[c] = topi[c];
#pragma unroll
                for (int a = 0; a < TOPK; a++) {
                    int best = a;
#pragma unroll
                    for (int b = a + 1; b < NCAND; b++)
                        if (rv[b] > rv[best] || (rv[b] == rv[best] && ri[b] < ri[best])) best = b;
                    double tvv = rv[a]; rv[a] = rv[best]; rv[best] = tvv;
                    int    tii = ri[a]; ri[a] = ri[best]; ri[best] = tii;
                }
                double mx = rv[0];
                float e0 = expf((float)(rv[0]-mx)), e1 = expf((float)(rv[1]-mx));
                float e2 = expf((float)(rv[2]-mx)), e3 = expf((float)(rv[3]-mx));
                float inv = 1.0f / (e0+e1+e2+e3);
                float* so = out + (size_t)row * TOPK;
                so[0]=e0*inv; so[1]=e1*inv; so[2]=e2*inv; so[3]=e3*inv;
                float* io = out + idx_base + (size_t)row * TOPK;
                io[0]=(float)ri[0]; io[1]=(float)ri[1]; io[2]=(float)ri[2]; io[3]=(float)ri[3];
            }
        }
    }
}

extern "C" void kernel_launch(void* const* d_in, const int* in_sizes, int n_in,
                              void* d_out, int out_size)
{
    const float* hidden = (const float*)d_in[0];
    const float* weight = (const float*)d_in[1];
    const float* bias   = (const float*)d_in[2];
    float* out = (float*)d_out;

    const int E = in_sizes[2];                 // 128
    const int H = in_sizes[1] / E;             // 2880
    const int T = in_sizes[0] / H;             // 16384
    const int idx_base = out_size / 2;
    const int nch = H / KC;                    // 45

    convert_weight_kernel<<<nch, 256>>>(weight, H);

    cudaFuncSetAttribute(router_mma_kernel,
                         cudaFuncAttributeMaxDynamicSharedMemorySize, SMEM_TOTAL);
    dim3 grid(T / BM);     // 128
    dim3 block(512);
    router_mma_kernel<<<grid, block, SMEM_TOTAL>>>(hidden, weight, bias, out, T, H, E, idx_base);
}